// round 17
// baseline (speedup 1.0000x reference)
#include <cuda_runtime.h>
#include <cuda_fp16.h>
#include <cstdint>
#include <math.h>

// Problem constants
#define BB 2
#define SS 2048
#define DD 1024
#define HH 16
#define HD 64
#define BH (BB*HH)          // 32
#define MROWS (BB*SS)       // 4096
#define LOG2E 1.4426950408889634f

// ---------------------------------------------------------------------------
// Scratch (static device globals: allocation-free)
// ---------------------------------------------------------------------------
__device__ __half g_q16[BH*SS*HD];    // Q single fp16 (exp2-domain scaled)
__device__ __half g_k16[BH*SS*HD];    // K single fp16
__device__ __half g_v16[BH*SS*HD];    // V single fp16
__device__ __half g_x16[MROWS*DD];    // X single fp16
__device__ __half g_w1t[3*DD*DD];     // W1^T single fp16 [3072,1024]
__device__ __half g_w2t[DD*DD];       // W2^T single fp16 [1024,1024]
__device__ __half g_a16[MROWS*DD];    // attn out single fp16

// ---------------------------------------------------------------------------
// PTX helpers (sm_80-portable: mma.sync / ldmatrix / cp.async)
// ---------------------------------------------------------------------------
__device__ __forceinline__ uint32_t smem_to_u32(const void* p) {
    uint32_t a;
    asm("{ .reg .u64 t; cvta.to.shared.u64 t, %1; cvt.u32.u64 %0, t; }"
        : "=r"(a) : "l"(p));
    return a;
}
__device__ __forceinline__ void ldsm_x4(uint32_t* r, uint32_t addr) {
    asm volatile("ldmatrix.sync.aligned.m8n8.x4.shared.b16 {%0,%1,%2,%3}, [%4];"
                 : "=r"(r[0]), "=r"(r[1]), "=r"(r[2]), "=r"(r[3]) : "r"(addr));
}
__device__ __forceinline__ void ldsm_x4_t(uint32_t* r, uint32_t addr) {
    asm volatile("ldmatrix.sync.aligned.m8n8.x4.trans.shared.b16 {%0,%1,%2,%3}, [%4];"
                 : "=r"(r[0]), "=r"(r[1]), "=r"(r[2]), "=r"(r[3]) : "r"(addr));
}
__device__ __forceinline__ void mma_f16(float* c, const uint32_t* a, uint32_t b0, uint32_t b1) {
    asm volatile(
        "mma.sync.aligned.m16n8k16.row.col.f32.f16.f16.f32 "
        "{%0,%1,%2,%3}, {%4,%5,%6,%7}, {%8,%9}, {%0,%1,%2,%3};"
        : "+f"(c[0]), "+f"(c[1]), "+f"(c[2]), "+f"(c[3])
        : "r"(a[0]), "r"(a[1]), "r"(a[2]), "r"(a[3]), "r"(b0), "r"(b1));
}
__device__ __forceinline__ void cp_async16(uint32_t saddr, const void* gptr) {
    asm volatile("cp.async.cg.shared.global [%0], [%1], 16;" :: "r"(saddr), "l"(gptr));
}
#define CP_COMMIT()  asm volatile("cp.async.commit_group;" ::: "memory")
#define CP_WAIT(n)   asm volatile("cp.async.wait_group %0;" :: "n"(n) : "memory")

// XOR swizzle inside 128B rows: element chunk c (16B) of row r
#define SWZ(r, c) ((uint32_t)(r)*128u + ((((uint32_t)(c)) ^ ((uint32_t)(r) & 7u)) << 4))

// Fast exp2 on FMA pipe. t <= 0 expected.
__device__ __forceinline__ float fexp2(float t) {
    t = fmaxf(t, -126.0f);
    float kf = rintf(t);
    float f = t - kf;
    float p = 0.0013333558f;
    p = fmaf(p, f, 0.0096181291f);
    p = fmaf(p, f, 0.0555041087f);
    p = fmaf(p, f, 0.2402265069f);
    p = fmaf(p, f, 0.6931471806f);
    p = fmaf(p, f, 1.0f);
    return __int_as_float(__float_as_int(p) + (((int)kf) << 23));
}

// ---------------------------------------------------------------------------
// Conversion kernels
// ---------------------------------------------------------------------------
__global__ __launch_bounds__(256)
void conv_kernel(const float* __restrict__ x, __half* __restrict__ xh)
{
    int i = (blockIdx.x * 256 + threadIdx.x) * 4;
    float4 v = *reinterpret_cast<const float4*>(x + i);
    __half2 a = __floats2half2_rn(v.x, v.y);
    __half2 b = __floats2half2_rn(v.z, v.w);
    *reinterpret_cast<__half2*>(xh + i)     = a;
    *reinterpret_cast<__half2*>(xh + i + 2) = b;
}

// W[K,N] fp32 -> WT single fp16 [N,K]
__global__ __launch_bounds__(256)
void tconv_kernel(const float* __restrict__ W, __half* __restrict__ WT, int K, int N)
{
    __shared__ float t[32][33];
    const int k0 = blockIdx.y * 32, n0 = blockIdx.x * 32;
    const int tx = threadIdx.x & 31, ty = threadIdx.x >> 5;
    #pragma unroll
    for (int i = 0; i < 4; i++)
        t[ty + i * 8][tx] = W[(size_t)(k0 + ty + i * 8) * N + n0 + tx];
    __syncthreads();
    #pragma unroll
    for (int i = 0; i < 4; i++) {
        int n = ty + i * 8;
        WT[(size_t)(n0 + n) * K + k0 + tx] = __float2half_rn(t[tx][n]);
    }
}

// ---------------------------------------------------------------------------
// mma.sync GEMM: D = A[M,K] @ B[N,K]^T + bias (single fp16 operands).
// BM=BN=128, BK=64 (128B rows, XOR swizzle). 8 warps (2x4), warp tile 64x32,
// 2 CTAs/SM. 3-stage cp.async pipeline, ONE __syncthreads per chunk
// (loads for chunk c+2 issued after compute; target buffer last read at c-1,
// separated from writers by the top-of-loop barrier).
// EPI=0: Q (scaled, exp2-domain) / K / V single-fp16 head-major. EPI=1: fp32 C.
// ---------------------------------------------------------------------------
#define TILE_B  16384           // 128 rows * 128B
#define STAGE_B 32768           // 2 tiles (A, B)
#define NSTG    3

template<int EPI>
__global__ __launch_bounds__(256, 2)
void mma_gemm(const __half* __restrict__ As, const __half* __restrict__ Bs,
              const float* __restrict__ bias, float* __restrict__ C,
              int N, int K)
{
    extern __shared__ char dsm[];
    const uint32_t sb = smem_to_u32(dsm);

    const int tid = threadIdx.x;
    const int wid = tid >> 5;
    const int lane = tid & 31;
    const int bm = blockIdx.y;
    const int bn = blockIdx.x;
    const int wm = wid & 1;
    const int wn = wid >> 1;

    const __half* gA = As + (size_t)bm * 128 * K;
    const __half* gB = Bs + (size_t)bn * 128 * K;

    auto load_stage = [&](int stage, int k0) {
        uint32_t sdst = sb + stage * STAGE_B;
        #pragma unroll
        for (int i = 0; i < 4; i++) {
            int ch = tid + i * 256;
            int r = ch >> 3, c = ch & 7;
            cp_async16(sdst + SWZ(r, c), gA + (size_t)r * K + k0 + c * 8);
            cp_async16(sdst + TILE_B + SWZ(r, c), gB + (size_t)r * K + k0 + c * 8);
        }
    };

    float acc[4][4][4];
    #pragma unroll
    for (int mt = 0; mt < 4; mt++)
        #pragma unroll
        for (int nt = 0; nt < 4; nt++)
            #pragma unroll
            for (int r = 0; r < 4; r++) acc[mt][nt][r] = 0.0f;

    const int NCH = K >> 6;    // K/64

    load_stage(0, 0);
    CP_COMMIT();
    load_stage(1, 64);
    CP_COMMIT();

    const int bg = lane >> 3;

    for (int c = 0; c < NCH; c++) {
        if (c + 1 < NCH) { CP_WAIT(1); } else { CP_WAIT(0); }
        __syncthreads();

        const int stage = c % NSTG;
        const uint32_t sA = sb + stage * STAGE_B;
        const uint32_t sB = sA + TILE_B;

        #pragma unroll
        for (int ks = 0; ks < 4; ks++) {
            uint32_t bf[2][4];
            #pragma unroll
            for (int nt2 = 0; nt2 < 2; nt2++) {
                int row = wn * 32 + nt2 * 16 + (lane & 7) + ((bg >> 1) << 3);
                ldsm_x4(bf[nt2], sB + SWZ(row, ks * 2 + (bg & 1)));
            }
            #pragma unroll
            for (int mt = 0; mt < 4; mt++) {
                uint32_t af[4];
                int row = wm * 64 + mt * 16 + (lane & 15);
                int cc = ks * 2 + (lane >> 4);
                ldsm_x4(af, sA + SWZ(row, cc));
                #pragma unroll
                for (int nt = 0; nt < 4; nt++)
                    mma_f16(acc[mt][nt], af, bf[nt >> 1][(nt & 1) * 2], bf[nt >> 1][(nt & 1) * 2 + 1]);
            }
        }

        if (c + 2 < NCH) {
            load_stage((c + 2) % NSTG, (c + 2) * 64);
            CP_COMMIT();
        }
    }

    // Epilogue: pair (r, r+1) = same row, adjacent cols -> wide stores
    #pragma unroll
    for (int mt = 0; mt < 4; mt++) {
        #pragma unroll
        for (int nt = 0; nt < 4; nt++) {
            #pragma unroll
            for (int rp = 0; rp < 2; rp++) {
                int m = bm * 128 + wm * 64 + mt * 16 + (lane >> 2) + rp * 8;
                int n = bn * 128 + wn * 32 + nt * 8 + (lane & 3) * 2;   // even
                float v0 = acc[mt][nt][rp * 2 + 0] + __ldg(&bias[n]);
                float v1 = acc[mt][nt][rp * 2 + 1] + __ldg(&bias[n + 1]);
                if (EPI == 0) {
                    int part = n >> 10;
                    int b = m >> 11;
                    int s = m & 2047;
                    int col = n & 1023;
                    int hh = col >> 6;
                    int d = col & 63;                      // even
                    size_t idx = (((size_t)(b * 16 + hh) * 2048) + s) * 64 + d;
                    __half* dst;
                    if (part == 0) {
                        v0 *= 0.125f * LOG2E;              // scale + exp2-domain fold
                        v1 *= 0.125f * LOG2E;
                        dst = g_q16;
                    } else if (part == 1) {
                        dst = g_k16;
                    } else {
                        dst = g_v16;
                    }
                    __half2 hp = __floats2half2_rn(v0, v1);
                    *reinterpret_cast<__half2*>(&dst[idx]) = hp;
                } else {
                    float2 o = make_float2(v0, v1);
                    *reinterpret_cast<float2*>(&C[(size_t)m * N + n]) = o;
                }
            }
        }
    }
}

// ---------------------------------------------------------------------------
// Tensor-core flash attention: all single fp16 (Q, K, P, V).
// Bq=128, Bk=64, 8 warps (warp = 16 q-rows), 2 CTAs/SM.
// 3-stage KV pipeline, ONE __syncthreads per k-tile.
// smem: Q 16KB + 3 stages x 16KB = 64KB per CTA.
// ---------------------------------------------------------------------------
__global__ __launch_bounds__(256, 2)
void flash_mma()
{
    extern __shared__ char fsm[];
    const uint32_t sb = smem_to_u32(fsm);
    const uint32_t sQ = sb;

    const int tid = threadIdx.x;
    const int lane = tid & 31;
    const int wid = tid >> 5;
    const int qt = 15 - blockIdx.x;       // heavy tiles first
    const int bh = blockIdx.y;

    const size_t qoff = ((size_t)bh * SS + qt * 128) * HD;

    auto load_Q = [&]() {
        #pragma unroll
        for (int i = 0; i < 4; i++) {
            int ch = tid + i * 256;
            int r = ch >> 3, c = ch & 7;
            cp_async16(sQ + SWZ(r, c), g_q16 + qoff + (size_t)r * 64 + c * 8);
        }
    };
    auto load_KV = [&](int stage, int kt) {
        uint32_t sbase = sb + 16384 + stage * 16384;
        size_t off = ((size_t)bh * SS + kt * 64) * HD;
        const __half* srcs[2] = { g_k16 + off, g_v16 + off };
        #pragma unroll
        for (int b = 0; b < 2; b++)
            #pragma unroll
            for (int i = 0; i < 2; i++) {
                int ch = tid + i * 256;
                int r = ch >> 3, c = ch & 7;
                cp_async16(sbase + b * 8192 + SWZ(r, c), srcs[b] + (size_t)r * 64 + c * 8);
            }
    };

    const int nkt = 2 * qt + 2;

    load_Q();
    load_KV(0, 0);
    CP_COMMIT();
    load_KV(1, 1);     // nkt >= 2 always
    CP_COMMIT();

    uint32_t qf[4][4];
    float oacc[8][4];
    #pragma unroll
    for (int nt = 0; nt < 8; nt++)
        #pragma unroll
        for (int j = 0; j < 4; j++) oacc[nt][j] = 0.0f;
    float m_s[2] = {-1e30f, -1e30f};
    float l_s[2] = {0.0f, 0.0f};

    for (int kt = 0; kt < nkt; kt++) {
        if (kt + 1 < nkt) { CP_WAIT(1); } else { CP_WAIT(0); }
        __syncthreads();

        if (kt == 0) {
            #pragma unroll
            for (int t = 0; t < 4; t++) {
                int row = wid * 16 + (lane & 15);
                int c = t * 2 + (lane >> 4);
                ldsm_x4(qf[t], sQ + SWZ(row, c));
            }
        }

        const int stage = kt % NSTG;
        const uint32_t stK = sb + 16384 + stage * 16384;
        const uint32_t stV = stK + 8192;

        float sacc[8][4];
        #pragma unroll
        for (int nt = 0; nt < 8; nt++)
            #pragma unroll
            for (int j = 0; j < 4; j++) sacc[nt][j] = 0.0f;

        // ---- S = Q K^T (single fp16) ----
        #pragma unroll
        for (int t = 0; t < 4; t++) {
            uint32_t k4[4][4];
            const int g = lane >> 3;
            #pragma unroll
            for (int p = 0; p < 4; p++) {
                int row = p * 16 + (lane & 7) + ((g >> 1) << 3);
                int c = t * 2 + (g & 1);
                ldsm_x4(k4[p], stK + SWZ(row, c));
            }
            #pragma unroll
            for (int p = 0; p < 4; p++) {
                mma_f16(sacc[2*p],   qf[t], k4[p][0], k4[p][1]);
                mma_f16(sacc[2*p+1], qf[t], k4[p][2], k4[p][3]);
            }
        }

        if (kt >= 2 * qt) {
            int r0 = qt * 128 + wid * 16 + (lane >> 2);
            #pragma unroll
            for (int nt = 0; nt < 8; nt++)
                #pragma unroll
                for (int j = 0; j < 4; j++) {
                    int row = r0 + (j >> 1) * 8;
                    int col = kt * 64 + nt * 8 + (lane & 3) * 2 + (j & 1);
                    if (col > row) sacc[nt][j] = -1e30f;
                }
        }

        float rmax[2] = {-1e30f, -1e30f};
        #pragma unroll
        for (int nt = 0; nt < 8; nt++) {
            rmax[0] = fmaxf(rmax[0], fmaxf(sacc[nt][0], sacc[nt][1]));
            rmax[1] = fmaxf(rmax[1], fmaxf(sacc[nt][2], sacc[nt][3]));
        }
        #pragma unroll
        for (int h = 0; h < 2; h++) {
            rmax[h] = fmaxf(rmax[h], __shfl_xor_sync(0xffffffffu, rmax[h], 1));
            rmax[h] = fmaxf(rmax[h], __shfl_xor_sync(0xffffffffu, rmax[h], 2));
        }
        float corr[2];
        #pragma unroll
        for (int h = 0; h < 2; h++) {
            float mnew = fmaxf(m_s[h], rmax[h]);
            corr[h] = fexp2(m_s[h] - mnew);
            m_s[h] = mnew;
        }

        // P single fp16
        uint32_t phpk[8][2];
        float rsum[2] = {0.0f, 0.0f};
        #pragma unroll
        for (int nt = 0; nt < 8; nt++) {
            #pragma unroll
            for (int h = 0; h < 2; h++) {
                float p0 = fexp2(sacc[nt][2*h]   - m_s[h]);
                float p1 = fexp2(sacc[nt][2*h+1] - m_s[h]);
                rsum[h] += p0 + p1;
                __half2 hp = __floats2half2_rn(p0, p1);
                phpk[nt][h] = *reinterpret_cast<uint32_t*>(&hp);
            }
        }
        #pragma unroll
        for (int h = 0; h < 2; h++) {
            rsum[h] += __shfl_xor_sync(0xffffffffu, rsum[h], 1);
            rsum[h] += __shfl_xor_sync(0xffffffffu, rsum[h], 2);
            l_s[h] = l_s[h] * corr[h] + rsum[h];
        }
        #pragma unroll
        for (int nt = 0; nt < 8; nt++) {
            oacc[nt][0] *= corr[0];
            oacc[nt][1] *= corr[0];
            oacc[nt][2] *= corr[1];
            oacc[nt][3] *= corr[1];
        }

        // ---- O += P V ----
        #pragma unroll
        for (int t = 0; t < 4; t++) {
            uint32_t pa[4] = { phpk[2*t][0], phpk[2*t][1], phpk[2*t+1][0], phpk[2*t+1][1] };
            uint32_t v4[4][4];
            #pragma unroll
            for (int p = 0; p < 4; p++) {
                int row = t * 16 + (lane & 15);
                int c = 2 * p + (lane >> 4);
                ldsm_x4_t(v4[p], stV + SWZ(row, c));
            }
            #pragma unroll
            for (int p = 0; p < 4; p++) {
                mma_f16(oacc[2*p],   pa, v4[p][0], v4[p][1]);
                mma_f16(oacc[2*p+1], pa, v4[p][2], v4[p][3]);
            }
        }

        if (kt + 2 < nkt) {
            load_KV((kt + 2) % NSTG, kt + 2);
            CP_COMMIT();
        }
    }

    const int b = bh >> 4;
    const int head = bh & 15;
    float inv[2] = {1.0f / l_s[0], 1.0f / l_s[1]};
    #pragma unroll
    for (int h = 0; h < 2; h++) {
        int srow = qt * 128 + wid * 16 + (lane >> 2) + h * 8;
        size_t base = ((size_t)(b * SS + srow)) * DD + head * 64 + (lane & 3) * 2;
        #pragma unroll
        for (int nt = 0; nt < 8; nt++) {
            __half2 hp = __floats2half2_rn(oacc[nt][2*h] * inv[h],
                                           oacc[nt][2*h+1] * inv[h]);
            *reinterpret_cast<__half2*>(g_a16 + base + nt * 8) = hp;
        }
    }
}

// ---------------------------------------------------------------------------
extern "C" void kernel_launch(void* const* d_in, const int* in_sizes, int n_in,
                              void* d_out, int out_size)
{
    (void)in_sizes; (void)n_in; (void)out_size;
    const float* x   = (const float*)d_in[0];
    const float* w1  = (const float*)d_in[1];
    const float* b1  = (const float*)d_in[2];
    const float* w2  = (const float*)d_in[3];
    const float* b2  = (const float*)d_in[4];
    float* out = (float*)d_out;

    const int SMEM_DYN = NSTG * STAGE_B;       // 98304
    const int SMEM_FL  = 65536;                // Q 16KB + 3 x 16KB
    cudaFuncSetAttribute((const void*)mma_gemm<0>, cudaFuncAttributeMaxDynamicSharedMemorySize, SMEM_DYN);
    cudaFuncSetAttribute((const void*)mma_gemm<1>, cudaFuncAttributeMaxDynamicSharedMemorySize, SMEM_DYN);
    cudaFuncSetAttribute((const void*)flash_mma, cudaFuncAttributeMaxDynamicSharedMemorySize, SMEM_FL);

    void *p_x16, *p_w1t, *p_w2t, *p_a16;
    cudaGetSymbolAddress(&p_x16, g_x16);
    cudaGetSymbolAddress(&p_w1t, g_w1t);
    cudaGetSymbolAddress(&p_w2t, g_w2t);
    cudaGetSymbolAddress(&p_a16, g_a16);

    conv_kernel<<<MROWS * DD / 1024, 256>>>(x, (__half*)p_x16);
    tconv_kernel<<<dim3(3 * DD / 32, DD / 32), 256>>>(w1, (__half*)p_w1t, DD, 3 * DD);
    tconv_kernel<<<dim3(DD / 32, DD / 32), 256>>>(w2, (__half*)p_w2t, DD, DD);

    // QKV: single fp16, one uniform launch (grid 24 x 32)
    mma_gemm<0><<<dim3(3 * DD / 128, MROWS / 128), 256, SMEM_DYN>>>(
        (const __half*)p_x16, (const __half*)p_w1t, b1, nullptr, 3 * DD, DD);

    flash_mma<<<dim3(SS / 128, BH), 256, SMEM_FL>>>();

    // Projection: single fp16 attn x single fp16 W2
    mma_gemm<1><<<dim3(DD / 128, MROWS / 128), 256, SMEM_DYN>>>(
        (const __half*)p_a16, (const __half*)p_w2t, b2, out, DD, DD);
}